// round 12
// baseline (speedup 1.0000x reference)
#include <cuda_runtime.h>
#include <cuda_bf16.h>

#define NNODES 1024
#define NEDGES 65536
#define STATE  1024
#define HID    64
#define POOLC  256
#define INSZ   (NNODES * POOLC)
#define NH     1024
#define ACT    2

// -------- scratch (zero at load; consumer-zeroed across replays) --------
__device__ float g_agg4[4][NNODES * HID]; // zeroed by k_gemv prologue after read
__device__ float g_cnt4[4][NNODES];       // zeroed by k_gemv prologue after read
__device__ float g_w2p[HID * 256];        // pooled W2 (recomputed each run)
__device__ float g_b2p[256];              // pooled b2
__device__ float g_part[32 * 256];        // gemv partials; zeroed by tail block
__device__ float g_z3[129];               // z3 + value (written by tail block)
__device__ unsigned g_done;               // gemv completion counter (tail resets)

// ======== K1: EdgeConv aggregation (+ pooled-W2 blocks appended) ========
// blocks [0,2048): edge work (2 edges/thread, 16 threads/edge, 4 replicas)
// blocks [2048,2112): w2p row (b-2048); row<32 also zeros g_part row
__global__ __launch_bounds__(256) void k_edge(const float* __restrict__ x,
                                              const int* __restrict__ ei,
                                              const float* __restrict__ W1,
                                              const float* __restrict__ b1,
                                              const float* __restrict__ W2,
                                              const float* __restrict__ b2) {
    int t = threadIdx.x;
    int blk = blockIdx.x;

    if (blk >= 2048) {  // ---- pooled W2 / b2 / zero partials ----
        int k = blk - 2048, j = t;
        float4 v = *(const float4*)&W2[k * STATE + 4 * j];
        g_w2p[k * 256 + j] = 0.25f * (v.x + v.y + v.z + v.w);
        if (k < 32) g_part[k * 256 + j] = 0.f;
        if (k == 0) {
            float4 bb = *(const float4*)&b2[4 * j];
            g_b2p[j] = 0.25f * (bb.x + bb.y + bb.z + bb.w);
        }
        return;
    }

    __shared__ float4 sW1[4][16];
    __shared__ float4 sb1[16];
    __shared__ int sflag;
    if (t == 0) sflag = 0;
    if (t < 64) ((float4*)sW1)[t] = ((const float4*)W1)[t];
    if (t < 16) sb1[t] = ((const float4*)b1)[t];
    __syncthreads();
    if (t < 64 && ei[2 * t + 1] != 0) sflag = 1;   // int64 detection, per block
    __syncthreads();
    int is64 = !sflag;

    int gid = blk * 256 + t;
    int g = gid & 15;
    int r = blk & 3;
    float4 w0 = sW1[0][g], w1 = sW1[1][g], w2 = sW1[2][g], w3 = sW1[3][g];
    float4 b = sb1[g];

#pragma unroll
    for (int half = 0; half < 2; half++) {
        int e = (gid >> 4) + half * (NEDGES / 2);
        int s, d;
        if (is64) {
            const long long* e64 = (const long long*)ei;
            s = (int)e64[e];
            d = (int)e64[NEDGES + e];
        } else {
            s = ei[e];
            d = ei[NEDGES + e];
        }
        s &= (NNODES - 1);
        d &= (NNODES - 1);

        float xi0 = x[2 * d], xi1 = x[2 * d + 1];
        float dx = x[2 * s] - xi0;
        float dy = x[2 * s + 1] - xi1;

        float4 h;
        h.x = fmaxf(b.x + xi0 * w0.x + xi1 * w1.x + dx * w2.x + dy * w3.x, 0.f);
        h.y = fmaxf(b.y + xi0 * w0.y + xi1 * w1.y + dx * w2.y + dy * w3.y, 0.f);
        h.z = fmaxf(b.z + xi0 * w0.z + xi1 * w1.z + dx * w2.z + dy * w3.z, 0.f);
        h.w = fmaxf(b.w + xi0 * w0.w + xi1 * w1.w + dx * w2.w + dy * w3.w, 0.f);

        atomicAdd((float4*)&g_agg4[r][d * HID + 4 * g], h);
        if (g == 0) atomicAdd(&g_cnt4[r][d], 1.0f);
    }
}

// ======== K2: fused pool + split-K GEMV + full trunk in last block ========
__global__ __launch_bounds__(256, 2) void k_gemv(const float* __restrict__ W3,
                                                 const float* __restrict__ b3,
                                                 const float* __restrict__ W4,
                                                 const float* __restrict__ b4,
                                                 const float* __restrict__ W5,
                                                 const float* __restrict__ b5,
                                                 const float* __restrict__ Wv,
                                                 const float* __restrict__ bv) {
    __shared__ float mh[4][HID];
    __shared__ float scnt[4];
    __shared__ float has[4];
    __shared__ float sz[1024];
    __shared__ float part[4][256];
    __shared__ int slast;
    int t = threadIdx.x;
    int bb = blockIdx.x;

    // ---- prologue: build z0 slice for nodes 4bb..4bb+3; zero agg scratch ----
    {
        int n = t >> 6, k = t & 63;
        int node = 4 * bb + n;
        int idx = node * HID + k;
        float a = g_agg4[0][idx] + g_agg4[1][idx] + g_agg4[2][idx] + g_agg4[3][idx];
        g_agg4[0][idx] = 0.f; g_agg4[1][idx] = 0.f;
        g_agg4[2][idx] = 0.f; g_agg4[3][idx] = 0.f;
        mh[n][k] = a;
        if (t < 4) {
            int nd = 4 * bb + t;
            float c = g_cnt4[0][nd] + g_cnt4[1][nd] + g_cnt4[2][nd] + g_cnt4[3][nd];
            g_cnt4[0][nd] = 0.f; g_cnt4[1][nd] = 0.f;
            g_cnt4[2][nd] = 0.f; g_cnt4[3][nd] = 0.f;
            scnt[t] = fmaxf(c, 1.0f);
            has[t] = (c > 0.f) ? 1.f : 0.f;
        }
        __syncthreads();
        mh[n][k] *= __frcp_rn(scnt[n]);
        __syncthreads();

        float a0 = 0.f, a1 = 0.f, a2 = 0.f, a3 = 0.f;
#pragma unroll 8
        for (int kk = 0; kk < HID; kk++) {
            float w = g_w2p[kk * 256 + t];
            a0 += mh[0][kk] * w;
            a1 += mh[1][kk] * w;
            a2 += mh[2][kk] * w;
            a3 += mh[3][kk] * w;
        }
        float bp = g_b2p[t];
        sz[t]       = a0 + bp * has[0];
        sz[256 + t] = a1 + bp * has[1];
        sz[512 + t] = a2 + bp * has[2];
        sz[768 + t] = a3 + bp * has[3];
        __syncthreads();
    }

    // ---- streaming GEMV over 1024 k-rows ----
    {
        int k0 = bb * 1024;
        int q = t >> 6, c = t & 63;
        float4 a0 = make_float4(0.f, 0.f, 0.f, 0.f);
        float4 a1 = a0, a2 = a0, a3 = a0;
        const float* base = W3 + (size_t)(k0 + q) * 256 + 4 * c;
#pragma unroll 8
        for (int k = 0; k < 256; k += 4) {
            float4 w0 = __ldcs((const float4*)(base + (size_t)(k + 0) * 1024));
            float4 w1 = __ldcs((const float4*)(base + (size_t)(k + 1) * 1024));
            float4 w2 = __ldcs((const float4*)(base + (size_t)(k + 2) * 1024));
            float4 w3 = __ldcs((const float4*)(base + (size_t)(k + 3) * 1024));
            float z0v = sz[4 * (k + 0) + q];
            float z1v = sz[4 * (k + 1) + q];
            float z2v = sz[4 * (k + 2) + q];
            float z3v = sz[4 * (k + 3) + q];
            a0.x += z0v * w0.x; a0.y += z0v * w0.y; a0.z += z0v * w0.z; a0.w += z0v * w0.w;
            a1.x += z1v * w1.x; a1.y += z1v * w1.y; a1.z += z1v * w1.z; a1.w += z1v * w1.w;
            a2.x += z2v * w2.x; a2.y += z2v * w2.y; a2.z += z2v * w2.z; a2.w += z2v * w2.w;
            a3.x += z3v * w3.x; a3.y += z3v * w3.y; a3.z += z3v * w3.z; a3.w += z3v * w3.w;
        }
        a0.x += a1.x + a2.x + a3.x;
        a0.y += a1.y + a2.y + a3.y;
        a0.z += a1.z + a2.z + a3.z;
        a0.w += a1.w + a2.w + a3.w;
        ((float4*)part[t >> 6])[t & 63] = a0;
    }
    __syncthreads();

    float s = part[0][t] + part[1][t] + part[2][t] + part[3][t];
    atomicAdd(&g_part[(bb & 31) * 256 + t], s);

    // ---- elect last block ----
    __threadfence();
    __syncthreads();
    if (t == 0) {
        unsigned r = atomicAdd(&g_done, 1u);
        slast = (r == 255u);
    }
    __syncthreads();
    if (!slast) return;
    if (t == 0) g_done = 0;
    __threadfence();

    // ---- trunk: z1 -> W4 -> z2 -> W5 -> z3 -> value (single block) ----
    __shared__ float z1[256];
    __shared__ float z2[256];
    __shared__ float z3s[128];
    {
        float a = 0.f;
#pragma unroll
        for (int j = 0; j < 32; j++) {
            a += g_part[j * 256 + t];
            g_part[j * 256 + t] = 0.f;   // self-zero for next replay
        }
        a += b3[t];
        z1[t] = (a > 0.f) ? a : 0.01f * a;
    }
    __syncthreads();
    {
        float a = 0.f;
#pragma unroll 8
        for (int k = 0; k < 256; k++) a += z1[k] * W4[k * 256 + t];
        a += b4[t];
        z2[t] = (a > 0.f) ? a : 0.01f * a;
    }
    __syncthreads();
    {
        // 2 threads per output col: t = (half<<7) | h
        int h = t & 127, half = t >> 7;
        float a = 0.f;
#pragma unroll 8
        for (int k = 0; k < 128; k++) a += z2[half * 128 + k] * W5[(half * 128 + k) * 128 + h];
        ((float*)part)[half * 128 + h] = a;
    }
    __syncthreads();
    if (t < 128) {
        float v = ((float*)part)[t] + ((float*)part)[128 + t] + b5[t];
        v = (v > 0.f) ? v : 0.01f * v;
        z3s[t] = v;
        g_z3[t] = v;
    }
    __syncthreads();
    if (t < 32) {
        float v = z3s[t] * Wv[t] + z3s[t + 32] * Wv[t + 32]
                + z3s[t + 64] * Wv[t + 64] + z3s[t + 96] * Wv[t + 96];
#pragma unroll
        for (int off = 16; off; off >>= 1) v += __shfl_down_sync(0xFFFFFFFFu, v, off);
        if (t == 0) g_z3[128] = v + bv[0];
    }
}

// ======== K3: dueling heads ========
__global__ __launch_bounds__(256) void k_q(const float* __restrict__ Wa,
                                           const float* __restrict__ ba,
                                           float* __restrict__ out) {
    __shared__ float z3[129];
    int t = threadIdx.x;
    if (t < 129) z3[t] = g_z3[t];
    __syncthreads();

    int warp = t >> 5, lane = t & 31;
    int n = blockIdx.x * 8 + warp;

    const float4* w = (const float4*)(Wa + (size_t)n * 256);
    float4 u = w[lane];
    float4 v = w[lane + 32];
    int f = 2 * lane;
    float a0 = z3[f] * u.x + z3[f + 1] * u.z + z3[64 + f] * v.x + z3[65 + f] * v.z;
    float a1 = z3[f] * u.y + z3[f + 1] * u.w + z3[64 + f] * v.y + z3[65 + f] * v.w;
#pragma unroll
    for (int off = 16; off; off >>= 1) {
        a0 += __shfl_down_sync(0xFFFFFFFFu, a0, off);
        a1 += __shfl_down_sync(0xFFFFFFFFu, a1, off);
    }
    if (lane == 0) {
        float adv0 = a0 + ba[2 * n];
        float adv1 = a1 + ba[2 * n + 1];
        float val = z3[128];
        float m = 0.5f * (adv0 + adv1);
        out[2 * n]     = val + adv0 - m;
        out[2 * n + 1] = val + adv1 - m;
    }
}

extern "C" void kernel_launch(void* const* d_in, const int* in_sizes, int n_in,
                              void* d_out, int out_size) {
    const float* x   = (const float*)d_in[0];
    const int*   ei  = (const int*)d_in[1];
    const float* W1  = (const float*)d_in[2];
    const float* b1  = (const float*)d_in[3];
    const float* W2  = (const float*)d_in[4];
    const float* b2  = (const float*)d_in[5];
    const float* W3  = (const float*)d_in[6];
    const float* b3  = (const float*)d_in[7];
    const float* W4  = (const float*)d_in[8];
    const float* b4  = (const float*)d_in[9];
    const float* W5  = (const float*)d_in[10];
    const float* b5  = (const float*)d_in[11];
    const float* Wv  = (const float*)d_in[12];
    const float* bv  = (const float*)d_in[13];
    const float* Wa  = (const float*)d_in[14];
    const float* ba  = (const float*)d_in[15];
    float* out = (float*)d_out;

    k_edge<<<2112, 256>>>(x, ei, W1, b1, W2, b2);
    k_gemv<<<INSZ / 1024, 256>>>(W3, b3, W4, b4, W5, b5, Wv, bv);
    k_q<<<NH / 8, 256>>>(Wa, ba, out);
}

// round 15
// speedup vs baseline: 1.1040x; 1.1040x over previous
#include <cuda_runtime.h>
#include <cuda_bf16.h>

#define NNODES 1024
#define NEDGES 65536
#define STATE  1024
#define HID    64
#define POOLC  256
#define INSZ   (NNODES * POOLC)
#define NH     1024
#define ACT    2
#define NREP   8

// -------- scratch (zero at load; consumer-zeroed across replays) --------
__device__ float g_agg[NREP][NNODES * HID]; // zeroed by k_gemv prologue
__device__ float g_cnt[NREP][NNODES];       // zeroed by k_gemv prologue
__device__ float g_w2p[HID * 256];          // pooled W2
__device__ float g_b2p[256];                // pooled b2
__device__ float g_part[16 * 256];          // gemv partials; zeroed by k_w2p
__device__ float g_acc4[256];               // zeroed by k_w2p
__device__ float g_acc5[128];               // zeroed by k_w2p
__device__ int   g_is64;

// -------- K0: pooled W2/b2 + small-scratch zero + dtype detect --------
__global__ __launch_bounds__(256) void k_w2p(const float* __restrict__ W2,
                                             const float* __restrict__ b2,
                                             const int* __restrict__ ei32) {
    int k = blockIdx.x;
    int j = threadIdx.x;
    float4 v = *(const float4*)&W2[k * STATE + 4 * j];
    g_w2p[k * 256 + j] = 0.25f * (v.x + v.y + v.z + v.w);
    if (k < 16) g_part[k * 256 + j] = 0.f;
    if (k == 0) {
        float4 bb = *(const float4*)&b2[4 * j];
        g_b2p[j] = 0.25f * (bb.x + bb.y + bb.z + bb.w);
    }
    if (k == 1) g_acc4[j] = 0.f;
    if (k == 2 && j < 128) g_acc5[j] = 0.f;
    if (k == 3 && j == 0) {
        int all0 = 1;
        for (int i = 0; i < 64; i++)
            if (ei32[2 * i + 1] != 0) { all0 = 0; break; }
        g_is64 = all0;
    }
}

// -------- K1: EdgeConv aggregation (float4 RED, 8 replicas, 2 edges/thread) --------
__global__ __launch_bounds__(256) void k_edge(const float* __restrict__ x,
                                              const int* __restrict__ ei,
                                              const float* __restrict__ W1,
                                              const float* __restrict__ b1) {
    __shared__ float4 sW1[4][16];
    __shared__ float4 sb1[16];
    int t = threadIdx.x;
    if (t < 64) ((float4*)sW1)[t] = ((const float4*)W1)[t];
    if (t < 16) sb1[t] = ((const float4*)b1)[t];
    __syncthreads();

    int gid = blockIdx.x * blockDim.x + t;
    int g = gid & 15;
    int r = blockIdx.x & (NREP - 1);
    float4 w0 = sW1[0][g], w1 = sW1[1][g], w2 = sW1[2][g], w3 = sW1[3][g];
    float4 b = sb1[g];

#pragma unroll
    for (int half = 0; half < 2; half++) {
        int e = (gid >> 4) + half * (NEDGES / 2);
        int s, d;
        if (g_is64) {
            const long long* e64 = (const long long*)ei;
            s = (int)e64[e];
            d = (int)e64[NEDGES + e];
        } else {
            s = ei[e];
            d = ei[NEDGES + e];
        }
        s &= (NNODES - 1);
        d &= (NNODES - 1);

        float xi0 = x[2 * d], xi1 = x[2 * d + 1];
        float dx = x[2 * s] - xi0;
        float dy = x[2 * s + 1] - xi1;

        float4 h;
        h.x = fmaxf(b.x + xi0 * w0.x + xi1 * w1.x + dx * w2.x + dy * w3.x, 0.f);
        h.y = fmaxf(b.y + xi0 * w0.y + xi1 * w1.y + dx * w2.y + dy * w3.y, 0.f);
        h.z = fmaxf(b.z + xi0 * w0.z + xi1 * w1.z + dx * w2.z + dy * w3.z, 0.f);
        h.w = fmaxf(b.w + xi0 * w0.w + xi1 * w1.w + dx * w2.w + dy * w3.w, 0.f);

        atomicAdd((float4*)&g_agg[r][d * HID + 4 * g], h);
        if (g == 0) atomicAdd(&g_cnt[r][d], 1.0f);
    }
}

// -------- K2: fused pool + split-K GEMV over W3[262144,256] --------
// 256 blocks x 256 threads; block b owns nodes 4b..4b+3 and k-rows [1024b,1024b+1024)
__global__ __launch_bounds__(256, 2) void k_gemv(const float* __restrict__ W3) {
    __shared__ float mh[4][HID];
    __shared__ float scnt[4];
    __shared__ float has[4];
    __shared__ float sz[1024];
    __shared__ float part[4][256];
    int t = threadIdx.x;
    int bb = blockIdx.x;

    // ---- prologue: build z0 slice for nodes 4bb..4bb+3; zero agg scratch ----
    {
        int n = t >> 6, k = t & 63;
        int node = 4 * bb + n;
        int idx = node * HID + k;
        float a = 0.f;
#pragma unroll
        for (int rr = 0; rr < NREP; rr++) {
            a += g_agg[rr][idx];
            g_agg[rr][idx] = 0.f;
        }
        mh[n][k] = a;
        if (t < 4) {
            int nd = 4 * bb + t;
            float c = 0.f;
#pragma unroll
            for (int rr = 0; rr < NREP; rr++) {
                c += g_cnt[rr][nd];
                g_cnt[rr][nd] = 0.f;
            }
            scnt[t] = fmaxf(c, 1.0f);
            has[t] = (c > 0.f) ? 1.f : 0.f;
        }
        __syncthreads();
        mh[n][k] *= __frcp_rn(scnt[n]);
        __syncthreads();

        float a0 = 0.f, a1 = 0.f, a2 = 0.f, a3 = 0.f;
#pragma unroll 8
        for (int kk = 0; kk < HID; kk++) {
            float w = g_w2p[kk * 256 + t];
            a0 += mh[0][kk] * w;
            a1 += mh[1][kk] * w;
            a2 += mh[2][kk] * w;
            a3 += mh[3][kk] * w;
        }
        float bp = g_b2p[t];
        sz[t]       = a0 + bp * has[0];
        sz[256 + t] = a1 + bp * has[1];
        sz[512 + t] = a2 + bp * has[2];
        sz[768 + t] = a3 + bp * has[3];
        __syncthreads();
    }

    // ---- streaming GEMV over 1024 k-rows ----
    int k0 = bb * 1024;
    int q = t >> 6, c = t & 63;
    float4 a0 = make_float4(0.f, 0.f, 0.f, 0.f);
    float4 a1 = a0, a2 = a0, a3 = a0;
    const float* base = W3 + (size_t)(k0 + q) * 256 + 4 * c;
#pragma unroll 8
    for (int k = 0; k < 256; k += 4) {
        float4 w0 = __ldcs((const float4*)(base + (size_t)(k + 0) * 1024));
        float4 w1 = __ldcs((const float4*)(base + (size_t)(k + 1) * 1024));
        float4 w2 = __ldcs((const float4*)(base + (size_t)(k + 2) * 1024));
        float4 w3 = __ldcs((const float4*)(base + (size_t)(k + 3) * 1024));
        float z0v = sz[4 * (k + 0) + q];
        float z1v = sz[4 * (k + 1) + q];
        float z2v = sz[4 * (k + 2) + q];
        float z3v = sz[4 * (k + 3) + q];
        a0.x += z0v * w0.x; a0.y += z0v * w0.y; a0.z += z0v * w0.z; a0.w += z0v * w0.w;
        a1.x += z1v * w1.x; a1.y += z1v * w1.y; a1.z += z1v * w1.z; a1.w += z1v * w1.w;
        a2.x += z2v * w2.x; a2.y += z2v * w2.y; a2.z += z2v * w2.z; a2.w += z2v * w2.w;
        a3.x += z3v * w3.x; a3.y += z3v * w3.y; a3.z += z3v * w3.z; a3.w += z3v * w3.w;
    }
    a0.x += a1.x + a2.x + a3.x;
    a0.y += a1.y + a2.y + a3.y;
    a0.z += a1.z + a2.z + a3.z;
    a0.w += a1.w + a2.w + a3.w;
    ((float4*)part[q])[c] = a0;
    __syncthreads();

    float s = part[0][t] + part[1][t] + part[2][t] + part[3][t];
    atomicAdd(&g_part[(bb & 15) * 256 + t], s);
}

// -------- K3: z1 = leaky(reduce(partials)+b3); partial z2 over W4 slice --------
__global__ __launch_bounds__(256) void k_trunk1(const float* __restrict__ b3,
                                                const float* __restrict__ W4) {
    __shared__ float z1[256];
    int t = threadIdx.x;
    float a = 0.f;
#pragma unroll
    for (int j = 0; j < 16; j++) a += g_part[j * 256 + t];
    a += b3[t];
    z1[t] = (a > 0.f) ? a : 0.01f * a;
    __syncthreads();

    int r0 = blockIdx.x * 8;
    float acc = 0.f;
#pragma unroll
    for (int k = 0; k < 8; k++) acc += z1[r0 + k] * W4[(r0 + k) * 256 + t];
    atomicAdd(&g_acc4[t], acc);
}

// -------- K4: z2 = leaky(acc4+b4); partial z3 over W5 slice --------
__global__ __launch_bounds__(256) void k_trunk2(const float* __restrict__ b4,
                                                const float* __restrict__ W5) {
    __shared__ float z2[256];
    int t = threadIdx.x;
    float v = g_acc4[t] + b4[t];
    z2[t] = (v > 0.f) ? v : 0.01f * v;
    __syncthreads();

    if (t < 128) {
        int r0 = blockIdx.x * 16;
        float acc = 0.f;
#pragma unroll
        for (int k = 0; k < 16; k++) acc += z2[r0 + k] * W5[(r0 + k) * 128 + t];
        atomicAdd(&g_acc5[t], acc);
    }
}

// -------- K5: dueling heads (z3+value recomputed per block) --------
__global__ __launch_bounds__(256) void k_q(const float* __restrict__ b5,
                                           const float* __restrict__ Wv,
                                           const float* __restrict__ bv,
                                           const float* __restrict__ Wa,
                                           const float* __restrict__ ba,
                                           float* __restrict__ out) {
    __shared__ float z3[128];
    __shared__ float sval;
    int t = threadIdx.x;
    if (t < 128) {
        float v = g_acc5[t] + b5[t];
        v = (v > 0.f) ? v : 0.01f * v;
        z3[t] = v;
    }
    __syncthreads();
    if (t < 32) {
        float s = z3[t] * Wv[t] + z3[t + 32] * Wv[t + 32]
                + z3[t + 64] * Wv[t + 64] + z3[t + 96] * Wv[t + 96];
#pragma unroll
        for (int off = 16; off; off >>= 1) s += __shfl_down_sync(0xFFFFFFFFu, s, off);
        if (t == 0) sval = s + bv[0];
    }
    __syncthreads();

    int warp = t >> 5, lane = t & 31;
    int n = blockIdx.x * 8 + warp;

    const float4* w = (const float4*)(Wa + (size_t)n * 256);
    float4 u = w[lane];
    float4 v = w[lane + 32];
    int f = 2 * lane;
    float a0 = z3[f] * u.x + z3[f + 1] * u.z + z3[64 + f] * v.x + z3[65 + f] * v.z;
    float a1 = z3[f] * u.y + z3[f + 1] * u.w + z3[64 + f] * v.y + z3[65 + f] * v.w;
#pragma unroll
    for (int off = 16; off; off >>= 1) {
        a0 += __shfl_down_sync(0xFFFFFFFFu, a0, off);
        a1 += __shfl_down_sync(0xFFFFFFFFu, a1, off);
    }
    if (lane == 0) {
        float adv0 = a0 + ba[2 * n];
        float adv1 = a1 + ba[2 * n + 1];
        float val = sval;
        float m = 0.5f * (adv0 + adv1);
        out[2 * n]     = val + adv0 - m;
        out[2 * n + 1] = val + adv1 - m;
    }
}

extern "C" void kernel_launch(void* const* d_in, const int* in_sizes, int n_in,
                              void* d_out, int out_size) {
    const float* x   = (const float*)d_in[0];
    const int*   ei  = (const int*)d_in[1];
    const float* W1  = (const float*)d_in[2];
    const float* b1  = (const float*)d_in[3];
    const float* W2  = (const float*)d_in[4];
    const float* b2  = (const float*)d_in[5];
    const float* W3  = (const float*)d_in[6];
    const float* b3  = (const float*)d_in[7];
    const float* W4  = (const float*)d_in[8];
    const float* b4  = (const float*)d_in[9];
    const float* W5  = (const float*)d_in[10];
    const float* b5  = (const float*)d_in[11];
    const float* Wv  = (const float*)d_in[12];
    const float* bv  = (const float*)d_in[13];
    const float* Wa  = (const float*)d_in[14];
    const float* ba  = (const float*)d_in[15];
    float* out = (float*)d_out;

    k_w2p<<<64, 256>>>(W2, b2, ei);
    k_edge<<<(NEDGES * 16) / (256 * 2), 256>>>(x, ei, W1, b1);
    k_gemv<<<INSZ / 1024, 256>>>(W3);
    k_trunk1<<<32, 256>>>(b3, W4);
    k_trunk2<<<16, 256>>>(b4, W5);
    k_q<<<NH / 8, 256>>>(b5, Wv, bv, Wa, ba, out);
}